// round 16
// baseline (speedup 1.0000x reference)
#include <cuda_runtime.h>
#include <cuda_bf16.h>
#include <math.h>
#include <stdint.h>

// ---------------------------------------------------------------------------
// Problem constants
// ---------------------------------------------------------------------------
#define SEQ    16
#define DIN    2048
#define DOUT   1128
#define NT     560          // C(16,3)
#define NSUP   5
#define NSEQ   6            // 5 support + 1 query
#define NROWS  96           // 6 seqs * 16 frames
#define NCOL   6768         // 2 (K,V) * 3 parts * 1128
#define KV_OFF 3384
#define LN_EPS 1e-5f

// proj pipeline (tf32, unchanged)
#define STAGE_F     4608
#define STAGE_B     (STAGE_F * 4)
#define SMEM_BYTES  (4 * STAGE_B)        // 73728 B

// score pipeline (bf16, BK=64): A 64 rows x 144 B + B 128 rows x 144 B
#define SC_STAGE_B  27648
#define SC_SMEM     (3 * SC_STAGE_B)     // 82944
#define SC_BOFF     9216

// dist pipeline (bf16, BK=64): A 64 x 144 B + B 64 x 272 B
#define DS_STAGE_B  26624
#define DS_SMEM     (3 * DS_STAGE_B)     // 79872
#define DS_BOFF     9216

// ---------------------------------------------------------------------------
// Scratch (device globals -- no allocation allowed)
// ---------------------------------------------------------------------------
__device__ float          g_X[NROWS * DIN];        // tf32-pre-rounded
__device__ float          g_Y[NROWS * NCOL];       // full fp32
__device__ __nv_bfloat16  g_Kb[NSEQ * NT * DOUT];  // bf16 keys (LN output)
__device__ __nv_bfloat16  g_Vb[NSEQ * NT * DOUT];  // bf16 values
__device__ float          g_S[NSUP * NT * NT];     // fp32 scores
__device__ __nv_bfloat16  g_A[NSUP * NT * NT];     // bf16 attention weights
__device__ int            g_tup[NT * 3];

// ---------------------------------------------------------------------------
// helpers
// ---------------------------------------------------------------------------
__device__ __forceinline__ void mma_tf32(float* c, const uint32_t* a, const uint32_t* b) {
    asm volatile(
        "mma.sync.aligned.m16n8k8.row.col.f32.tf32.tf32.f32 "
        "{%0,%1,%2,%3}, {%4,%5,%6,%7}, {%8,%9}, {%0,%1,%2,%3};\n"
        : "+f"(c[0]), "+f"(c[1]), "+f"(c[2]), "+f"(c[3])
        : "r"(a[0]), "r"(a[1]), "r"(a[2]), "r"(a[3]), "r"(b[0]), "r"(b[1]));
}

__device__ __forceinline__ void mma_bf16(float* c, const uint32_t* a, const uint32_t* b) {
    asm volatile(
        "mma.sync.aligned.m16n8k16.row.col.f32.bf16.bf16.f32 "
        "{%0,%1,%2,%3}, {%4,%5,%6,%7}, {%8,%9}, {%0,%1,%2,%3};\n"
        : "+f"(c[0]), "+f"(c[1]), "+f"(c[2]), "+f"(c[3])
        : "r"(a[0]), "r"(a[1]), "r"(a[2]), "r"(a[3]), "r"(b[0]), "r"(b[1]));
}

__device__ __forceinline__ float rnd32(float f) {
    uint32_t r;
    asm("cvt.rna.tf32.f32 %0, %1;" : "=r"(r) : "f"(f));
    return __uint_as_float(r);
}

__device__ __forceinline__ uint32_t ldcvt(const uint32_t* p) {
    float f = __uint_as_float(*p);
    uint32_t r;
    asm("cvt.rna.tf32.f32 %0, %1;" : "=r"(r) : "f"(f));
    return r;
}

__device__ __forceinline__ void ldsm4(uint32_t addr, uint32_t& r0, uint32_t& r1,
                                      uint32_t& r2, uint32_t& r3) {
    asm volatile("ldmatrix.sync.aligned.m8n8.x4.shared.b16 {%0,%1,%2,%3}, [%4];"
                 : "=r"(r0), "=r"(r1), "=r"(r2), "=r"(r3) : "r"(addr));
}

__device__ __forceinline__ void ldsm4t(uint32_t addr, uint32_t& r0, uint32_t& r1,
                                       uint32_t& r2, uint32_t& r3) {
    asm volatile("ldmatrix.sync.aligned.m8n8.x4.trans.shared.b16 {%0,%1,%2,%3}, [%4];"
                 : "=r"(r0), "=r"(r1), "=r"(r2), "=r"(r3) : "r"(addr));
}

__device__ __forceinline__ void cp16(uint32_t saddr, const void* g, bool p) {
    asm volatile("cp.async.cg.shared.global [%0], [%1], 16, %2;"
                 :: "r"(saddr), "l"(g), "r"(p ? 16 : 0));
}
#define CP_COMMIT()  asm volatile("cp.async.commit_group;")
#define CP_WAIT1()   asm volatile("cp.async.wait_group 1;")
#define CP_WAIT2()   asm volatile("cp.async.wait_group 2;")

// ---------------------------------------------------------------------------
// Kernel 1: X = input + positional encoding (tf32 pre-rounded).
// ---------------------------------------------------------------------------
__global__ void build_x_kernel(const float* __restrict__ sup,
                               const float* __restrict__ qry,
                               float* __restrict__ out) {
    int r   = blockIdx.x;
    int tid = threadIdx.x;
    if (r == 0) {
        if (tid == 0) {
            int idx = 0;
            for (int i = 0; i < SEQ; i++)
                for (int j = i + 1; j < SEQ; j++)
                    for (int k = j + 1; k < SEQ; k++) {
                        g_tup[idx * 3 + 0] = i;
                        g_tup[idx * 3 + 1] = j;
                        g_tup[idx * 3 + 2] = k;
                        idx++;
                    }
        }
        if (tid < NSUP) out[tid] = 0.0f;
    }
    int f   = (r < 80) ? (r & 15) : (r - 80);
    const float* src = (r < 80) ? (sup + r * DIN) : (qry + (r - 80) * DIN);
    const float cexp = -logf(10000.0f) / (float)DIN;
    for (int j = tid; j < DIN / 2; j += blockDim.x) {
        float div = expf((float)(2 * j) * cexp);
        float ang = (float)f * div;
        g_X[r * DIN + 2 * j]     = rnd32(src[2 * j]     + 0.1f * sinf(ang));
        g_X[r * DIN + 2 * j + 1] = rnd32(src[2 * j + 1] + 0.1f * cosf(ang));
    }
}

// ---------------------------------------------------------------------------
// Kernel 2: Y[96,6768] = X[96,2048] @ W^T.  tf32 MMA (unchanged).
// ---------------------------------------------------------------------------
__global__ void __launch_bounds__(192) proj_kernel(const float* __restrict__ wk,
                                                   const float* __restrict__ wv) {
    extern __shared__ float smem[];
    uint32_t sbase = (uint32_t)__cvta_generic_to_shared(smem);
    const uint32_t* S = (const uint32_t*)smem;

    int tid  = threadIdx.x;
    int lane = tid & 31;
    int wid  = tid >> 5;
    int g    = lane >> 2;
    int tg   = lane & 3;
    int n0   = blockIdx.x * 32;

    const float* gb[6]; uint32_t so[6]; bool ex[6]; bool sok[6];
#pragma unroll
    for (int l = 0; l < 6; l++) {
        int idx = tid + l * 192;
        ex[l] = idx < 1024;
        gb[l] = g_X; so[l] = 0; sok[l] = false;
        if (!ex[l]) continue;
        if (idx < 768) {
            int r = idx >> 3, q = idx & 7;
            gb[l]  = g_X + r * DIN + 4 * q;
            so[l]  = r * 144 + q * 16;
            sok[l] = true;
        } else {
            int j = idx - 768;
            int r = j >> 3, q = j & 7;
            int cg = n0 + r;
            so[l] = 13824 + r * 144 + q * 16;
            if (cg < NCOL) {
                const float* base; int p, rr;
                if (cg < KV_OFF) { p = cg / DOUT; rr = cg - p * DOUT; base = wk; }
                else             { int c2 = cg - KV_OFF; p = c2 / DOUT; rr = c2 - p * DOUT; base = wv; }
                gb[l]  = base + rr * (3 * DIN) + p * DIN + 4 * q;
                sok[l] = true;
            }
        }
    }

    float acc[4][4];
#pragma unroll
    for (int nr = 0; nr < 4; nr++)
#pragma unroll
        for (int e = 0; e < 4; e++) acc[nr][e] = 0.0f;

    const int NKT = DIN / 32;   // 64
#pragma unroll
    for (int p = 0; p < 3; p++) {
        int k0 = p * 32;
        uint32_t boff = p * STAGE_B;
#pragma unroll
        for (int l = 0; l < 6; l++)
            if (ex[l]) cp16(sbase + boff + so[l], gb[l] + k0, sok[l]);
        CP_COMMIT();
    }

    for (int kt = 0; kt < NKT; kt++) {
        CP_WAIT2();
        __syncthreads();
        int kp = kt + 3;
        if (kp < NKT) {
            int k0 = kp * 32;
            uint32_t boff = (kp & 3) * STAGE_B;
#pragma unroll
            for (int l = 0; l < 6; l++)
                if (ex[l]) cp16(sbase + boff + so[l], gb[l] + k0, sok[l]);
        }
        CP_COMMIT();

        const uint32_t* As = S + (kt & 3) * STAGE_F;
        const uint32_t* Bs = As + 3456;
#pragma unroll
        for (int kk = 0; kk < 32; kk += 8) {
            uint32_t a[4];
            a[0] = As[(wid * 16 + g)     * 36 + kk + tg];
            a[1] = As[(wid * 16 + g + 8) * 36 + kk + tg];
            a[2] = As[(wid * 16 + g)     * 36 + kk + tg + 4];
            a[3] = As[(wid * 16 + g + 8) * 36 + kk + tg + 4];
#pragma unroll
            for (int nr = 0; nr < 4; nr++) {
                uint32_t b[2];
                b[0] = ldcvt(&Bs[(nr * 8 + g) * 36 + kk + tg]);
                b[1] = ldcvt(&Bs[(nr * 8 + g) * 36 + kk + tg + 4]);
                mma_tf32(acc[nr], a, b);
            }
        }
    }

#pragma unroll
    for (int nr = 0; nr < 4; nr++)
#pragma unroll
        for (int e = 0; e < 4; e++) {
            int row = wid * 16 + g + ((e >= 2) ? 8 : 0);
            int cg  = n0 + nr * 8 + 2 * tg + (e & 1);
            if (cg < NCOL) g_Y[row * NCOL + cg] = acc[nr][e];
        }
}

// ---------------------------------------------------------------------------
// Kernel 3: assemble per-tuple K (LN -> bf16) and V (bf16 only).
// ---------------------------------------------------------------------------
__global__ void __launch_bounds__(256) assemble_kernel(const float* __restrict__ bk,
                                                       const float* __restrict__ bv,
                                                       const float* __restrict__ gamma,
                                                       const float* __restrict__ beta) {
    int t   = blockIdx.x;
    int n   = blockIdx.y;
    int tid = threadIdx.x;
    int lane = tid & 31, warp = tid >> 5;

    int i0 = g_tup[t * 3 + 0];
    int i1 = g_tup[t * 3 + 1];
    int i2 = g_tup[t * 3 + 2];
    const float* y0 = g_Y + (n * SEQ + i0) * NCOL;
    const float* y1 = g_Y + (n * SEQ + i1) * NCOL;
    const float* y2 = g_Y + (n * SEQ + i2) * NCOL;

    float kr[5];
    float s1 = 0.0f, s2 = 0.0f;
#pragma unroll
    for (int k = 0; k < 5; k++) {
        int d = tid + k * 256;
        if (k < 4 || tid < (DOUT - 1024)) {
            float v = y0[d] + y1[DOUT + d] + y2[2 * DOUT + d] + bk[d];
            kr[k] = v; s1 += v; s2 += v * v;
            float vv = y0[KV_OFF + d] + y1[KV_OFF + DOUT + d] + y2[KV_OFF + 2 * DOUT + d] + bv[d];
            g_Vb[(n * NT + t) * DOUT + d] = __float2bfloat16_rn(vv);
        } else kr[k] = 0.0f;
    }
    __shared__ float r1[8], r2[8];
    __shared__ float mu_s, rs_s;
#pragma unroll
    for (int o = 16; o; o >>= 1) {
        s1 += __shfl_xor_sync(0xffffffffu, s1, o);
        s2 += __shfl_xor_sync(0xffffffffu, s2, o);
    }
    if (lane == 0) { r1[warp] = s1; r2[warp] = s2; }
    __syncthreads();
    if (tid == 0) {
        float a = 0.0f, b = 0.0f;
        for (int w = 0; w < 8; w++) { a += r1[w]; b += r2[w]; }
        float mu = a / (float)DOUT;
        float var = b / (float)DOUT - mu * mu;
        mu_s = mu;
        rs_s = rsqrtf(var + LN_EPS);
    }
    __syncthreads();
    float mu = mu_s, rs = rs_s;
#pragma unroll
    for (int k = 0; k < 5; k++) {
        int d = tid + k * 256;
        if (k < 4 || tid < (DOUT - 1024))
            g_Kb[(n * NT + t) * DOUT + d] =
                __float2bfloat16_rn((kr[k] - mu) * rs * gamma[d] + beta[d]);
    }
}

// ---------------------------------------------------------------------------
// Kernel 4: S = Kq . Kc^T * scale.  bf16 m16n8k16.  Block tile 64x128,
// 256 threads (8 warps, 2x4), warp tile 32x32, BK=64, 3-stage cp.async.
// Grid (9,5,5) = 225 blocks -> 2 blocks/SM resident (83 KB smem).
// ---------------------------------------------------------------------------
__global__ void __launch_bounds__(256) score_kernel(const int* __restrict__ labels) {
    extern __shared__ float smem[];
    uint32_t sbase = (uint32_t)__cvta_generic_to_shared(smem);

    int tid  = threadIdx.x;
    int lane = tid & 31;
    int wid  = tid >> 5;
    int wm   = wid & 1;               // m block 32*wm (0..1)
    int wn   = wid >> 1;              // n block 32*wn (0..3)
    int g    = lane >> 2;
    int tg   = lane & 3;

    int c  = blockIdx.z;
    int t0 = blockIdx.x * 64;
    int s0 = blockIdx.y * 128;
    int lab = labels[c];
    if (lab < 0) lab = 0; if (lab >= NSUP) lab = NSUP - 1;

    const __nv_bfloat16* Aq = g_Kb + (size_t)NSUP * NT * DOUT;
    const __nv_bfloat16* Bc = g_Kb + (size_t)lab * NT * DOUT;

    // loader: 1536 granules per stage (A 512 + B 1024), 6 slots/thread
    const __nv_bfloat16* gb[6]; uint32_t so[6]; int kthr[6]; bool sok[6];
#pragma unroll
    for (int l = 0; l < 6; l++) {
        int idx = tid + l * 256;
        if (idx < 512) {
            int r = idx >> 3, q = idx & 7;
            int row = t0 + r;
            sok[l]  = row < NT;
            gb[l]   = Aq + (size_t)(sok[l] ? row : 0) * DOUT + 8 * q;
            so[l]   = r * 144 + q * 16;
            kthr[l] = DOUT - 8 * q;
        } else {
            int j = idx - 512;
            int r = j >> 3, q = j & 7;
            int row = s0 + r;
            sok[l]  = row < NT;
            gb[l]   = Bc + (size_t)(sok[l] ? row : 0) * DOUT + 8 * q;
            so[l]   = SC_BOFF + r * 144 + q * 16;
            kthr[l] = DOUT - 8 * q;
        }
    }

    uint32_t aoff0 = (uint32_t)((wm * 32 + (lane & 15)) * 144 + (lane >> 4) * 16);
    uint32_t aoff1 = aoff0 + 16 * 144;
    uint32_t boffL = (uint32_t)(SC_BOFF + (wn * 32 + (lane >> 4) * 8 + (lane & 7)) * 144
                                + ((lane >> 3) & 1) * 16);

    float acc[2][4][4];
#pragma unroll
    for (int mi = 0; mi < 2; mi++)
#pragma unroll
        for (int ni = 0; ni < 4; ni++)
#pragma unroll
            for (int e = 0; e < 4; e++) acc[mi][ni][e] = 0.0f;

    const int NKT = (DOUT + 63) / 64;   // 18
#pragma unroll
    for (int p = 0; p < 2; p++) {
        int k0 = p * 64;
        uint32_t boff = p * SC_STAGE_B;
#pragma unroll
        for (int l = 0; l < 6; l++)
            cp16(sbase + boff + so[l], gb[l] + k0, sok[l] && (k0 < kthr[l]));
        CP_COMMIT();
    }

    for (int kt = 0; kt < NKT; kt++) {
        CP_WAIT1();
        __syncthreads();
        int kp = kt + 2;
        if (kp < NKT) {
            int k0 = kp * 64;
            uint32_t boff = (kp % 3) * SC_STAGE_B;
#pragma unroll
            for (int l = 0; l < 6; l++)
                cp16(sbase + boff + so[l], gb[l] + k0, sok[l] && (k0 < kthr[l]));
        }
        CP_COMMIT();

        uint32_t stg = sbase + (kt % 3) * SC_STAGE_B;
#pragma unroll
        for (int kq = 0; kq < 4; kq++) {          // four k16 groups, +32 B each
            uint32_t koff = kq * 32;
            uint32_t a[2][4];
            ldsm4(stg + aoff0 + koff, a[0][0], a[0][1], a[0][2], a[0][3]);
            ldsm4(stg + aoff1 + koff, a[1][0], a[1][1], a[1][2], a[1][3]);
            uint32_t b[4][2];
#pragma unroll
            for (int nb = 0; nb < 2; nb++) {      // each ldsm4 covers 2 n8-tiles
                uint32_t r0, r1, r2, r3;
                ldsm4(stg + boffL + nb * (16 * 144) + koff, r0, r1, r2, r3);
                b[nb * 2 + 0][0] = r0; b[nb * 2 + 0][1] = r1;
                b[nb * 2 + 1][0] = r2; b[nb * 2 + 1][1] = r3;
            }
#pragma unroll
            for (int mi = 0; mi < 2; mi++)
#pragma unroll
                for (int ni = 0; ni < 4; ni++)
                    mma_bf16(acc[mi][ni], a[mi], b[ni]);
        }
    }

    const float scale = rsqrtf((float)DOUT);
    float* Sc = g_S + (size_t)c * NT * NT;
#pragma unroll
    for (int mi = 0; mi < 2; mi++)
#pragma unroll
        for (int ni = 0; ni < 4; ni++)
#pragma unroll
            for (int e = 0; e < 4; e++) {
                int t = t0 + wm * 32 + mi * 16 + g + ((e >= 2) ? 8 : 0);
                int s = s0 + wn * 32 + ni * 8 + 2 * tg + (e & 1);
                if (t < NT && s < NT) Sc[(size_t)t * NT + s] = acc[mi][ni][e] * scale;
            }
}

// ---------------------------------------------------------------------------
// Kernel 5: row softmax; attn written to g_A as bf16.
// ---------------------------------------------------------------------------
__global__ void __launch_bounds__(256) softmax_kernel() {
    int lane = threadIdx.x & 31;
    int row  = blockIdx.x * 8 + (threadIdx.x >> 5);
    if (row >= NSUP * NT) return;
    const float* r = g_S + (size_t)row * NT;
    __nv_bfloat16* a = g_A + (size_t)row * NT;

    float m = -1e30f;
    for (int s = lane; s < NT; s += 32) m = fmaxf(m, r[s]);
#pragma unroll
    for (int o = 16; o; o >>= 1) m = fmaxf(m, __shfl_xor_sync(0xffffffffu, m, o));
    float sum = 0.0f;
    float ev[NT / 32 + 1];
    int cnt = 0;
    for (int s = lane; s < NT; s += 32) {
        float e = expf(r[s] - m);
        ev[cnt++] = e;
        sum += e;
    }
#pragma unroll
    for (int o = 16; o; o >>= 1) sum += __shfl_xor_sync(0xffffffffu, sum, o);
    float inv = 1.0f / sum;
    cnt = 0;
    for (int s = lane; s < NT; s += 32) a[s] = __float2bfloat16_rn(ev[cnt++] * inv);
}

// ---------------------------------------------------------------------------
// Kernel 6: P = attn @ Vc (bf16), accumulate (q_v - P)^2 (Vq bf16).
// Block tile 64(t) x 128(d), 256 threads (8 warps, 2x4), warp 32x32,
// BK=64 over s, 3-stage.  A ldmatrix, B ldmatrix.trans.
// Grid (9,9,5) = 405 blocks -> 2 blocks/SM resident (80 KB smem).
// ---------------------------------------------------------------------------
__global__ void __launch_bounds__(256) dist_kernel(const int* __restrict__ labels,
                                                   float* __restrict__ out) {
    extern __shared__ float smem[];
    __shared__ float red[8];
    uint32_t sbase = (uint32_t)__cvta_generic_to_shared(smem);

    int tid  = threadIdx.x;
    int lane = tid & 31;
    int wid  = tid >> 5;
    int wm   = wid & 1;               // t block 32*wm (0..1)
    int wn   = wid >> 1;              // d block 32*wn (0..3)
    int g    = lane >> 2;
    int tg   = lane & 3;

    int c  = blockIdx.z;
    int t0 = blockIdx.x * 64;
    int d0 = blockIdx.y * 128;
    int lab = labels[c];
    if (lab < 0) lab = 0; if (lab >= NSUP) lab = NSUP - 1;

    const __nv_bfloat16* Ag = g_A + (size_t)c * NT * NT;
    const __nv_bfloat16* Vc = g_Vb + (size_t)lab * NT * DOUT;
    const __nv_bfloat16* Vq = g_Vb + (size_t)NSUP * NT * DOUT;

    // loader: A 512 granules (64 t-rows x 8), B 1024 (64 s-rows x 16); 6/thread
    const __nv_bfloat16* gb[6]; uint32_t so[6]; int gstep[6]; int kthr[6]; bool sok[6];
#pragma unroll
    for (int l = 0; l < 6; l++) {
        int idx = tid + l * 256;
        if (idx < 512) {
            int r = idx >> 3, q = idx & 7;
            int row = t0 + r;
            sok[l]   = row < NT;
            gb[l]    = Ag + (size_t)(sok[l] ? row : 0) * NT + 8 * q;
            so[l]    = r * 144 + q * 16;
            gstep[l] = 1;
            kthr[l]  = NT - 8 * q;
        } else {
            int j = idx - 512;
            int r = j >> 4, q = j & 15;
            int d = d0 + 8 * q;
            sok[l]   = d < DOUT;
            gb[l]    = Vc + (size_t)r * DOUT + (sok[l] ? d : 0);
            so[l]    = DS_BOFF + r * 272 + q * 16;
            gstep[l] = DOUT;
            kthr[l]  = NT - r;
        }
    }

    uint32_t aoff0 = (uint32_t)((wm * 32 + (lane & 15)) * 144 + (lane >> 4) * 16);
    uint32_t aoff1 = aoff0 + 16 * 144;
    uint32_t boffL = (uint32_t)(DS_BOFF + (((lane >> 3) & 1) * 8 + (lane & 7)) * 272
                                + (wn * 32 + (lane >> 4) * 8) * 2);

    float acc[2][4][4];
#pragma unroll
    for (int mi = 0; mi < 2; mi++)
#pragma unroll
        for (int ni = 0; ni < 4; ni++)
#pragma unroll
            for (int e = 0; e < 4; e++) acc[mi][ni][e] = 0.0f;

    const int NKT = (NT + 63) / 64;   // 9
#pragma unroll
    for (int p = 0; p < 2; p++) {
        int k0 = p * 64;
        uint32_t boff = p * DS_STAGE_B;
#pragma unroll
        for (int l = 0; l < 6; l++)
            cp16(sbase + boff + so[l], gb[l] + (size_t)k0 * gstep[l],
                 sok[l] && (k0 < kthr[l]));
        CP_COMMIT();
    }

    for (int kt = 0; kt < NKT; kt++) {
        CP_WAIT1();
        __syncthreads();
        int kp = kt + 2;
        if (kp < NKT) {
            int k0 = kp * 64;
            uint32_t boff = (kp % 3) * DS_STAGE_B;
#pragma unroll
            for (int l = 0; l < 6; l++)
                cp16(sbase + boff + so[l], gb[l] + (size_t)k0 * gstep[l],
                     sok[l] && (k0 < kthr[l]));
        }
        CP_COMMIT();

        uint32_t stg = sbase + (kt % 3) * DS_STAGE_B;
#pragma unroll
        for (int kq = 0; kq < 4; kq++) {
            uint32_t koff  = kq * 32;          // A: +32 B along s
            uint32_t krow  = kq * 16 * 272;    // B: +16 k-rows
            uint32_t a[2][4];
            ldsm4(stg + aoff0 + koff, a[0][0], a[0][1], a[0][2], a[0][3]);
            ldsm4(stg + aoff1 + koff, a[1][0], a[1][1], a[1][2], a[1][3]);
            uint32_t b[4][2];
#pragma unroll
            for (int nb = 0; nb < 2; nb++) {
                uint32_t r0, r1, r2, r3;
                ldsm4t(stg + boffL + krow + nb * 32, r0, r1, r2, r3);
                b[nb * 2 + 0][0] = r0; b[nb * 2 + 0][1] = r1;
                b[nb * 2 + 1][0] = r2; b[nb * 2 + 1][1] = r3;
            }
#pragma unroll
            for (int mi = 0; mi < 2; mi++)
#pragma unroll
                for (int ni = 0; ni < 4; ni++)
                    mma_bf16(acc[mi][ni], a[mi], b[ni]);
        }
    }

    float loc = 0.0f;
#pragma unroll
    for (int mi = 0; mi < 2; mi++)
#pragma unroll
        for (int ni = 0; ni < 4; ni++)
#pragma unroll
            for (int e = 0; e < 4; e++) {
                int t = t0 + wm * 32 + mi * 16 + g + ((e >= 2) ? 8 : 0);
                int d = d0 + wn * 32 + ni * 8 + 2 * tg + (e & 1);
                if (t < NT && d < DOUT) {
                    float diff = __bfloat162float(Vq[(size_t)t * DOUT + d]) - acc[mi][ni][e];
                    loc += diff * diff;
                }
            }
#pragma unroll
    for (int o = 16; o; o >>= 1) loc += __shfl_xor_sync(0xffffffffu, loc, o);
    if (lane == 0) red[wid] = loc;
    __syncthreads();
    if (tid == 0) {
        float tot = 0.0f;
        for (int w = 0; w < 8; w++) tot += red[w];
        atomicAdd(out + c, -tot / (float)NT);
    }
}

// ---------------------------------------------------------------------------
// Launch
// ---------------------------------------------------------------------------
extern "C" void kernel_launch(void* const* d_in, const int* in_sizes, int n_in,
                              void* d_out, int out_size) {
    const float* sup   = (const float*)d_in[0];
    const float* qry   = (const float*)d_in[1];
    const int*   lab   = (const int*)d_in[2];
    const float* wk    = (const float*)d_in[3];
    const float* bk    = (const float*)d_in[4];
    const float* wv    = (const float*)d_in[5];
    const float* bv    = (const float*)d_in[6];
    const float* gamma = (const float*)d_in[7];
    const float* beta  = (const float*)d_in[8];
    float* out = (float*)d_out;

    cudaFuncSetAttribute(proj_kernel,  cudaFuncAttributeMaxDynamicSharedMemorySize, SMEM_BYTES);
    cudaFuncSetAttribute(score_kernel, cudaFuncAttributeMaxDynamicSharedMemorySize, SC_SMEM);
    cudaFuncSetAttribute(dist_kernel,  cudaFuncAttributeMaxDynamicSharedMemorySize, DS_SMEM);

    build_x_kernel<<<NROWS, 256>>>(sup, qry, out);
    proj_kernel<<<(NCOL + 31) / 32, 192, SMEM_BYTES>>>(wk, wv);
    assemble_kernel<<<dim3(NT, NSEQ), 256>>>(bk, bv, gamma, beta);
    score_kernel<<<dim3(9, 5, NSUP), 256, SC_SMEM>>>(lab);
    softmax_kernel<<<(NSUP * NT + 7) / 8, 256>>>();
    dist_kernel<<<dim3(9, 9, NSUP), 256, DS_SMEM>>>(lab, out);
}

// round 17
// speedup vs baseline: 1.5667x; 1.5667x over previous
#include <cuda_runtime.h>
#include <cuda_bf16.h>
#include <math.h>
#include <stdint.h>

// ---------------------------------------------------------------------------
// Problem constants
// ---------------------------------------------------------------------------
#define SEQ    16
#define DIN    2048
#define DOUT   1128
#define NT     560          // C(16,3)
#define NSUP   5
#define NSEQ   6            // 5 support + 1 query
#define NROWS  96           // 6 seqs * 16 frames
#define NCOL   6768         // 2 (K,V) * 3 parts * 1128
#define KV_OFF 3384
#define LN_EPS 1e-5f

// proj pipeline (tf32, unchanged)
#define STAGE_F     4608
#define STAGE_B     (STAGE_F * 4)
#define SMEM_BYTES  (4 * STAGE_B)        // 73728 B

// score pipeline (bf16, BK=64): A 128 rows x 144 B + B 128 rows x 144 B
#define SC_STAGE_B  36864
#define SC_SMEM     (3 * SC_STAGE_B)     // 110592
#define SC_BOFF     18432

// dist pipeline (bf16, BK=64): A 128 x 144 B + B 64 x 272 B
#define DS_STAGE_B  35840
#define DS_SMEM     (3 * DS_STAGE_B)     // 107520
#define DS_BOFF     18432

// ---------------------------------------------------------------------------
// Scratch (device globals -- no allocation allowed)
// ---------------------------------------------------------------------------
__device__ float          g_X[NROWS * DIN];        // tf32-pre-rounded
__device__ float          g_Y[NROWS * NCOL];       // full fp32
__device__ __nv_bfloat16  g_Kb[NSEQ * NT * DOUT];  // bf16 keys (LN output)
__device__ __nv_bfloat16  g_Vb[NSEQ * NT * DOUT];  // bf16 values
__device__ float          g_S[NSUP * NT * NT];     // fp32 scores
__device__ __nv_bfloat16  g_A[NSUP * NT * NT];     // bf16 attention weights
__device__ int            g_tup[NT * 3];

// ---------------------------------------------------------------------------
// helpers
// ---------------------------------------------------------------------------
__device__ __forceinline__ void mma_tf32(float* c, const uint32_t* a, const uint32_t* b) {
    asm volatile(
        "mma.sync.aligned.m16n8k8.row.col.f32.tf32.tf32.f32 "
        "{%0,%1,%2,%3}, {%4,%5,%6,%7}, {%8,%9}, {%0,%1,%2,%3};\n"
        : "+f"(c[0]), "+f"(c[1]), "+f"(c[2]), "+f"(c[3])
        : "r"(a[0]), "r"(a[1]), "r"(a[2]), "r"(a[3]), "r"(b[0]), "r"(b[1]));
}

__device__ __forceinline__ void mma_bf16(float* c, const uint32_t* a, const uint32_t* b) {
    asm volatile(
        "mma.sync.aligned.m16n8k16.row.col.f32.bf16.bf16.f32 "
        "{%0,%1,%2,%3}, {%4,%5,%6,%7}, {%8,%9}, {%0,%1,%2,%3};\n"
        : "+f"(c[0]), "+f"(c[1]), "+f"(c[2]), "+f"(c[3])
        : "r"(a[0]), "r"(a[1]), "r"(a[2]), "r"(a[3]), "r"(b[0]), "r"(b[1]));
}

__device__ __forceinline__ float rnd32(float f) {
    uint32_t r;
    asm("cvt.rna.tf32.f32 %0, %1;" : "=r"(r) : "f"(f));
    return __uint_as_float(r);
}

__device__ __forceinline__ uint32_t ldcvt(const uint32_t* p) {
    float f = __uint_as_float(*p);
    uint32_t r;
    asm("cvt.rna.tf32.f32 %0, %1;" : "=r"(r) : "f"(f));
    return r;
}

__device__ __forceinline__ void ldsm4(uint32_t addr, uint32_t& r0, uint32_t& r1,
                                      uint32_t& r2, uint32_t& r3) {
    asm volatile("ldmatrix.sync.aligned.m8n8.x4.shared.b16 {%0,%1,%2,%3}, [%4];"
                 : "=r"(r0), "=r"(r1), "=r"(r2), "=r"(r3) : "r"(addr));
}

__device__ __forceinline__ void ldsm4t(uint32_t addr, uint32_t& r0, uint32_t& r1,
                                       uint32_t& r2, uint32_t& r3) {
    asm volatile("ldmatrix.sync.aligned.m8n8.x4.trans.shared.b16 {%0,%1,%2,%3}, [%4];"
                 : "=r"(r0), "=r"(r1), "=r"(r2), "=r"(r3) : "r"(addr));
}

__device__ __forceinline__ void cp16(uint32_t saddr, const void* g, bool p) {
    asm volatile("cp.async.cg.shared.global [%0], [%1], 16, %2;"
                 :: "r"(saddr), "l"(g), "r"(p ? 16 : 0));
}
#define CP_COMMIT()  asm volatile("cp.async.commit_group;")
#define CP_WAIT1()   asm volatile("cp.async.wait_group 1;")
#define CP_WAIT2()   asm volatile("cp.async.wait_group 2;")

// ---------------------------------------------------------------------------
// Kernel 1: X = input + positional encoding (tf32 pre-rounded).
// ---------------------------------------------------------------------------
__global__ void build_x_kernel(const float* __restrict__ sup,
                               const float* __restrict__ qry,
                               float* __restrict__ out) {
    int r   = blockIdx.x;
    int tid = threadIdx.x;
    if (r == 0) {
        if (tid == 0) {
            int idx = 0;
            for (int i = 0; i < SEQ; i++)
                for (int j = i + 1; j < SEQ; j++)
                    for (int k = j + 1; k < SEQ; k++) {
                        g_tup[idx * 3 + 0] = i;
                        g_tup[idx * 3 + 1] = j;
                        g_tup[idx * 3 + 2] = k;
                        idx++;
                    }
        }
        if (tid < NSUP) out[tid] = 0.0f;
    }
    int f   = (r < 80) ? (r & 15) : (r - 80);
    const float* src = (r < 80) ? (sup + r * DIN) : (qry + (r - 80) * DIN);
    const float cexp = -logf(10000.0f) / (float)DIN;
    for (int j = tid; j < DIN / 2; j += blockDim.x) {
        float div = expf((float)(2 * j) * cexp);
        float ang = (float)f * div;
        g_X[r * DIN + 2 * j]     = rnd32(src[2 * j]     + 0.1f * sinf(ang));
        g_X[r * DIN + 2 * j + 1] = rnd32(src[2 * j + 1] + 0.1f * cosf(ang));
    }
}

// ---------------------------------------------------------------------------
// Kernel 2: Y[96,6768] = X[96,2048] @ W^T.  tf32 MMA (unchanged).
// ---------------------------------------------------------------------------
__global__ void __launch_bounds__(192) proj_kernel(const float* __restrict__ wk,
                                                   const float* __restrict__ wv) {
    extern __shared__ float smem[];
    uint32_t sbase = (uint32_t)__cvta_generic_to_shared(smem);
    const uint32_t* S = (const uint32_t*)smem;

    int tid  = threadIdx.x;
    int lane = tid & 31;
    int wid  = tid >> 5;
    int g    = lane >> 2;
    int tg   = lane & 3;
    int n0   = blockIdx.x * 32;

    const float* gb[6]; uint32_t so[6]; bool ex[6]; bool sok[6];
#pragma unroll
    for (int l = 0; l < 6; l++) {
        int idx = tid + l * 192;
        ex[l] = idx < 1024;
        gb[l] = g_X; so[l] = 0; sok[l] = false;
        if (!ex[l]) continue;
        if (idx < 768) {
            int r = idx >> 3, q = idx & 7;
            gb[l]  = g_X + r * DIN + 4 * q;
            so[l]  = r * 144 + q * 16;
            sok[l] = true;
        } else {
            int j = idx - 768;
            int r = j >> 3, q = j & 7;
            int cg = n0 + r;
            so[l] = 13824 + r * 144 + q * 16;
            if (cg < NCOL) {
                const float* base; int p, rr;
                if (cg < KV_OFF) { p = cg / DOUT; rr = cg - p * DOUT; base = wk; }
                else             { int c2 = cg - KV_OFF; p = c2 / DOUT; rr = c2 - p * DOUT; base = wv; }
                gb[l]  = base + rr * (3 * DIN) + p * DIN + 4 * q;
                sok[l] = true;
            }
        }
    }

    float acc[4][4];
#pragma unroll
    for (int nr = 0; nr < 4; nr++)
#pragma unroll
        for (int e = 0; e < 4; e++) acc[nr][e] = 0.0f;

    const int NKT = DIN / 32;   // 64
#pragma unroll
    for (int p = 0; p < 3; p++) {
        int k0 = p * 32;
        uint32_t boff = p * STAGE_B;
#pragma unroll
        for (int l = 0; l < 6; l++)
            if (ex[l]) cp16(sbase + boff + so[l], gb[l] + k0, sok[l]);
        CP_COMMIT();
    }

    for (int kt = 0; kt < NKT; kt++) {
        CP_WAIT2();
        __syncthreads();
        int kp = kt + 3;
        if (kp < NKT) {
            int k0 = kp * 32;
            uint32_t boff = (kp & 3) * STAGE_B;
#pragma unroll
            for (int l = 0; l < 6; l++)
                if (ex[l]) cp16(sbase + boff + so[l], gb[l] + k0, sok[l]);
        }
        CP_COMMIT();

        const uint32_t* As = S + (kt & 3) * STAGE_F;
        const uint32_t* Bs = As + 3456;
#pragma unroll
        for (int kk = 0; kk < 32; kk += 8) {
            uint32_t a[4];
            a[0] = As[(wid * 16 + g)     * 36 + kk + tg];
            a[1] = As[(wid * 16 + g + 8) * 36 + kk + tg];
            a[2] = As[(wid * 16 + g)     * 36 + kk + tg + 4];
            a[3] = As[(wid * 16 + g + 8) * 36 + kk + tg + 4];
#pragma unroll
            for (int nr = 0; nr < 4; nr++) {
                uint32_t b[2];
                b[0] = ldcvt(&Bs[(nr * 8 + g) * 36 + kk + tg]);
                b[1] = ldcvt(&Bs[(nr * 8 + g) * 36 + kk + tg + 4]);
                mma_tf32(acc[nr], a, b);
            }
        }
    }

#pragma unroll
    for (int nr = 0; nr < 4; nr++)
#pragma unroll
        for (int e = 0; e < 4; e++) {
            int row = wid * 16 + g + ((e >= 2) ? 8 : 0);
            int cg  = n0 + nr * 8 + 2 * tg + (e & 1);
            if (cg < NCOL) g_Y[row * NCOL + cg] = acc[nr][e];
        }
}

// ---------------------------------------------------------------------------
// Kernel 3: assemble per-tuple K (LN -> bf16) and V (bf16 only).
// ---------------------------------------------------------------------------
__global__ void __launch_bounds__(256) assemble_kernel(const float* __restrict__ bk,
                                                       const float* __restrict__ bv,
                                                       const float* __restrict__ gamma,
                                                       const float* __restrict__ beta) {
    int t   = blockIdx.x;
    int n   = blockIdx.y;
    int tid = threadIdx.x;
    int lane = tid & 31, warp = tid >> 5;

    int i0 = g_tup[t * 3 + 0];
    int i1 = g_tup[t * 3 + 1];
    int i2 = g_tup[t * 3 + 2];
    const float* y0 = g_Y + (n * SEQ + i0) * NCOL;
    const float* y1 = g_Y + (n * SEQ + i1) * NCOL;
    const float* y2 = g_Y + (n * SEQ + i2) * NCOL;

    float kr[5];
    float s1 = 0.0f, s2 = 0.0f;
#pragma unroll
    for (int k = 0; k < 5; k++) {
        int d = tid + k * 256;
        if (k < 4 || tid < (DOUT - 1024)) {
            float v = y0[d] + y1[DOUT + d] + y2[2 * DOUT + d] + bk[d];
            kr[k] = v; s1 += v; s2 += v * v;
            float vv = y0[KV_OFF + d] + y1[KV_OFF + DOUT + d] + y2[KV_OFF + 2 * DOUT + d] + bv[d];
            g_Vb[(n * NT + t) * DOUT + d] = __float2bfloat16_rn(vv);
        } else kr[k] = 0.0f;
    }
    __shared__ float r1[8], r2[8];
    __shared__ float mu_s, rs_s;
#pragma unroll
    for (int o = 16; o; o >>= 1) {
        s1 += __shfl_xor_sync(0xffffffffu, s1, o);
        s2 += __shfl_xor_sync(0xffffffffu, s2, o);
    }
    if (lane == 0) { r1[warp] = s1; r2[warp] = s2; }
    __syncthreads();
    if (tid == 0) {
        float a = 0.0f, b = 0.0f;
        for (int w = 0; w < 8; w++) { a += r1[w]; b += r2[w]; }
        float mu = a / (float)DOUT;
        float var = b / (float)DOUT - mu * mu;
        mu_s = mu;
        rs_s = rsqrtf(var + LN_EPS);
    }
    __syncthreads();
    float mu = mu_s, rs = rs_s;
#pragma unroll
    for (int k = 0; k < 5; k++) {
        int d = tid + k * 256;
        if (k < 4 || tid < (DOUT - 1024))
            g_Kb[(n * NT + t) * DOUT + d] =
                __float2bfloat16_rn((kr[k] - mu) * rs * gamma[d] + beta[d]);
    }
}

// ---------------------------------------------------------------------------
// Kernel 4: S = Kq . Kc^T * scale.  bf16 m16n8k16.  128x128 block tile,
// 512 threads (16 warps, 4x4), warp tile 32x32, BK=64, 3-stage cp.async.
// (R15 configuration -- proven best.)
// ---------------------------------------------------------------------------
__global__ void __launch_bounds__(512) score_kernel(const int* __restrict__ labels) {
    extern __shared__ float smem[];
    uint32_t sbase = (uint32_t)__cvta_generic_to_shared(smem);

    int tid  = threadIdx.x;
    int lane = tid & 31;
    int wid  = tid >> 5;
    int wm   = wid & 3;               // m block 32*wm
    int wn   = wid >> 2;              // n block 32*wn (0..3)
    int g    = lane >> 2;
    int tg   = lane & 3;

    int c  = blockIdx.z;
    int t0 = blockIdx.x * 128;
    int s0 = blockIdx.y * 128;
    int lab = labels[c];
    if (lab < 0) lab = 0; if (lab >= NSUP) lab = NSUP - 1;

    const __nv_bfloat16* Aq = g_Kb + (size_t)NSUP * NT * DOUT;
    const __nv_bfloat16* Bc = g_Kb + (size_t)lab * NT * DOUT;

    // loader: 2048 granules per stage (A 1024 + B 1024), 4 slots/thread
    const __nv_bfloat16* gb[4]; uint32_t so[4]; int kthr[4]; bool sok[4];
#pragma unroll
    for (int l = 0; l < 4; l++) {
        int idx = tid + l * 512;
        if (idx < 1024) {
            int r = idx >> 3, q = idx & 7;
            int row = t0 + r;
            sok[l]  = row < NT;
            gb[l]   = Aq + (size_t)(sok[l] ? row : 0) * DOUT + 8 * q;
            so[l]   = r * 144 + q * 16;
            kthr[l] = DOUT - 8 * q;
        } else {
            int j = idx - 1024;
            int r = j >> 3, q = j & 7;
            int row = s0 + r;
            sok[l]  = row < NT;
            gb[l]   = Bc + (size_t)(sok[l] ? row : 0) * DOUT + 8 * q;
            so[l]   = SC_BOFF + r * 144 + q * 16;
            kthr[l] = DOUT - 8 * q;
        }
    }

    uint32_t aoff0 = (uint32_t)((wm * 32 + (lane & 15)) * 144 + (lane >> 4) * 16);
    uint32_t aoff1 = aoff0 + 16 * 144;
    uint32_t boffL = (uint32_t)(SC_BOFF + (wn * 32 + (lane >> 4) * 8 + (lane & 7)) * 144
                                + ((lane >> 3) & 1) * 16);

    float acc[2][4][4];
#pragma unroll
    for (int mi = 0; mi < 2; mi++)
#pragma unroll
        for (int ni = 0; ni < 4; ni++)
#pragma unroll
            for (int e = 0; e < 4; e++) acc[mi][ni][e] = 0.0f;

    const int NKT = (DOUT + 63) / 64;   // 18
#pragma unroll
    for (int p = 0; p < 2; p++) {
        int k0 = p * 64;
        uint32_t boff = p * SC_STAGE_B;
#pragma unroll
        for (int l = 0; l < 4; l++)
            cp16(sbase + boff + so[l], gb[l] + k0, sok[l] && (k0 < kthr[l]));
        CP_COMMIT();
    }

    for (int kt = 0; kt < NKT; kt++) {
        CP_WAIT1();
        __syncthreads();
        int kp = kt + 2;
        if (kp < NKT) {
            int k0 = kp * 64;
            uint32_t boff = (kp % 3) * SC_STAGE_B;
#pragma unroll
            for (int l = 0; l < 4; l++)
                cp16(sbase + boff + so[l], gb[l] + k0, sok[l] && (k0 < kthr[l]));
        }
        CP_COMMIT();

        uint32_t stg = sbase + (kt % 3) * SC_STAGE_B;
#pragma unroll
        for (int kq = 0; kq < 4; kq++) {          // four k16 groups, +32 B each
            uint32_t koff = kq * 32;
            uint32_t a[2][4];
            ldsm4(stg + aoff0 + koff, a[0][0], a[0][1], a[0][2], a[0][3]);
            ldsm4(stg + aoff1 + koff, a[1][0], a[1][1], a[1][2], a[1][3]);
            uint32_t b[4][2];
#pragma unroll
            for (int nb = 0; nb < 2; nb++) {      // each ldsm4 covers 2 n8-tiles
                uint32_t r0, r1, r2, r3;
                ldsm4(stg + boffL + nb * (16 * 144) + koff, r0, r1, r2, r3);
                b[nb * 2 + 0][0] = r0; b[nb * 2 + 0][1] = r1;
                b[nb * 2 + 1][0] = r2; b[nb * 2 + 1][1] = r3;
            }
#pragma unroll
            for (int mi = 0; mi < 2; mi++)
#pragma unroll
                for (int ni = 0; ni < 4; ni++)
                    mma_bf16(acc[mi][ni], a[mi], b[ni]);
        }
    }

    const float scale = rsqrtf((float)DOUT);
    float* Sc = g_S + (size_t)c * NT * NT;
#pragma unroll
    for (int mi = 0; mi < 2; mi++)
#pragma unroll
        for (int ni = 0; ni < 4; ni++)
#pragma unroll
            for (int e = 0; e < 4; e++) {
                int t = t0 + wm * 32 + mi * 16 + g + ((e >= 2) ? 8 : 0);
                int s = s0 + wn * 32 + ni * 8 + 2 * tg + (e & 1);
                if (t < NT && s < NT) Sc[(size_t)t * NT + s] = acc[mi][ni][e] * scale;
            }
}

// ---------------------------------------------------------------------------
// Kernel 5: row softmax; attn written to g_A as bf16.
// ---------------------------------------------------------------------------
__global__ void __launch_bounds__(256) softmax_kernel() {
    int lane = threadIdx.x & 31;
    int row  = blockIdx.x * 8 + (threadIdx.x >> 5);
    if (row >= NSUP * NT) return;
    const float* r = g_S + (size_t)row * NT;
    __nv_bfloat16* a = g_A + (size_t)row * NT;

    float m = -1e30f;
    for (int s = lane; s < NT; s += 32) m = fmaxf(m, r[s]);
#pragma unroll
    for (int o = 16; o; o >>= 1) m = fmaxf(m, __shfl_xor_sync(0xffffffffu, m, o));
    float sum = 0.0f;
    float ev[NT / 32 + 1];
    int cnt = 0;
    for (int s = lane; s < NT; s += 32) {
        float e = expf(r[s] - m);
        ev[cnt++] = e;
        sum += e;
    }
#pragma unroll
    for (int o = 16; o; o >>= 1) sum += __shfl_xor_sync(0xffffffffu, sum, o);
    float inv = 1.0f / sum;
    cnt = 0;
    for (int s = lane; s < NT; s += 32) a[s] = __float2bfloat16_rn(ev[cnt++] * inv);
}

// ---------------------------------------------------------------------------
// Kernel 6: P = attn @ Vc (bf16), accumulate (q_v - P)^2 (Vq bf16).
// 128(t) x 128(d) block tile, 512 threads, warp 32x32, BK=64 over s,
// 3-stage.  A ldmatrix, B ldmatrix.trans.  (R15 configuration.)
// ---------------------------------------------------------------------------
__global__ void __launch_bounds__(512) dist_kernel(const int* __restrict__ labels,
                                                   float* __restrict__ out) {
    extern __shared__ float smem[];
    __shared__ float red[16];
    uint32_t sbase = (uint32_t)__cvta_generic_to_shared(smem);

    int tid  = threadIdx.x;
    int lane = tid & 31;
    int wid  = tid >> 5;
    int wm   = wid & 3;
    int wn   = wid >> 2;              // 0..3 -> d block 32*wn
    int g    = lane >> 2;
    int tg   = lane & 3;

    int c  = blockIdx.z;
    int t0 = blockIdx.x * 128;
    int d0 = blockIdx.y * 128;
    int lab = labels[c];
    if (lab < 0) lab = 0; if (lab >= NSUP) lab = NSUP - 1;

    const __nv_bfloat16* Ag = g_A + (size_t)c * NT * NT;
    const __nv_bfloat16* Vc = g_Vb + (size_t)lab * NT * DOUT;
    const __nv_bfloat16* Vq = g_Vb + (size_t)NSUP * NT * DOUT;

    // loader: A 1024 granules (128 t-rows x 8), B 1024 (64 s-rows x 16); 4/thread
    const __nv_bfloat16* gb[4]; uint32_t so[4]; int gstep[4]; int kthr[4]; bool sok[4];
#pragma unroll
    for (int l = 0; l < 4; l++) {
        int idx = tid + l * 512;
        if (idx < 1024) {
            int r = idx >> 3, q = idx & 7;
            int row = t0 + r;
            sok[l]   = row < NT;
            gb[l]    = Ag + (size_t)(sok[l] ? row : 0) * NT + 8 * q;
            so[l]    = r * 144 + q * 16;
            gstep[l] = 1;
            kthr[l]  = NT - 8 * q;
        } else {
            int j = idx - 1024;
            int r = j >> 4, q = j & 15;
            int d = d0 + 8 * q;
            sok[l]   = d < DOUT;
            gb[l]    = Vc + (size_t)r * DOUT + (sok[l] ? d : 0);
            so[l]    = DS_BOFF + r * 272 + q * 16;
            gstep[l] = DOUT;
            kthr[l]  = NT - r;
        }
    }

    uint32_t aoff0 = (uint32_t)((wm * 32 + (lane & 15)) * 144 + (lane >> 4) * 16);
    uint32_t aoff1 = aoff0 + 16 * 144;
    uint32_t boffL = (uint32_t)(DS_BOFF + (((lane >> 3) & 1) * 8 + (lane & 7)) * 272
                                + (wn * 32 + (lane >> 4) * 8) * 2);

    float acc[2][4][4];
#pragma unroll
    for (int mi = 0; mi < 2; mi++)
#pragma unroll
        for (int ni = 0; ni < 4; ni++)
#pragma unroll
            for (int e = 0; e < 4; e++) acc[mi][ni][e] = 0.0f;

    const int NKT = (NT + 63) / 64;   // 9
#pragma unroll
    for (int p = 0; p < 2; p++) {
        int k0 = p * 64;
        uint32_t boff = p * DS_STAGE_B;
#pragma unroll
        for (int l = 0; l < 4; l++)
            cp16(sbase + boff + so[l], gb[l] + (size_t)k0 * gstep[l],
                 sok[l] && (k0 < kthr[l]));
        CP_COMMIT();
    }

    for (int kt = 0; kt < NKT; kt++) {
        CP_WAIT1();
        __syncthreads();
        int kp = kt + 2;
        if (kp < NKT) {
            int k0 = kp * 64;
            uint32_t boff = (kp % 3) * DS_STAGE_B;
#pragma unroll
            for (int l = 0; l < 4; l++)
                cp16(sbase + boff + so[l], gb[l] + (size_t)k0 * gstep[l],
                     sok[l] && (k0 < kthr[l]));
        }
        CP_COMMIT();

        uint32_t stg = sbase + (kt % 3) * DS_STAGE_B;
#pragma unroll
        for (int kq = 0; kq < 4; kq++) {
            uint32_t koff  = kq * 32;          // A: +32 B along s
            uint32_t krow  = kq * 16 * 272;    // B: +16 k-rows
            uint32_t a[2][4];
            ldsm4(stg + aoff0 + koff, a[0][0], a[0][1], a[0][2], a[0][3]);
            ldsm4(stg + aoff1 + koff, a[1][0], a[1][1], a[1][2], a[1][3]);
            uint32_t b[4][2];
#pragma unroll
            for (int nb = 0; nb < 2; nb++) {
                uint32_t r0, r1, r2, r3;
                ldsm4t(stg + boffL + krow + nb * 32, r0, r1, r2, r3);
                b[nb * 2 + 0][0] = r0; b[nb * 2 + 0][1] = r1;
                b[nb * 2 + 1][0] = r2; b[nb * 2 + 1][1] = r3;
            }
#pragma unroll
            for (int mi = 0; mi < 2; mi++)
#pragma unroll
                for (int ni = 0; ni < 4; ni++)
                    mma_bf16(acc[mi][ni], a[mi], b[ni]);
        }
    }

    float loc = 0.0f;
#pragma unroll
    for (int mi = 0; mi < 2; mi++)
#pragma unroll
        for (int ni = 0; ni < 4; ni++)
#pragma unroll
            for (int e = 0; e < 4; e++) {
                int t = t0 + wm * 32 + mi * 16 + g + ((e >= 2) ? 8 : 0);
                int d = d0 + wn * 32 + ni * 8 + 2 * tg + (e & 1);
                if (t < NT && d < DOUT) {
                    float diff = __bfloat162float(Vq[(size_t)t * DOUT + d]) - acc[mi][ni][e];
                    loc += diff * diff;
                }
            }
#pragma unroll
    for (int o = 16; o; o >>= 1) loc += __shfl_xor_sync(0xffffffffu, loc, o);
    if (lane == 0) red[wid] = loc;
    __syncthreads();
    if (tid == 0) {
        float tot = 0.0f;
        for (int w = 0; w < 16; w++) tot += red[w];
        atomicAdd(out + c, -tot / (float)NT);
    }
}

// ---------------------------------------------------------------------------
// Launch
// ---------------------------------------------------------------------------
extern "C" void kernel_launch(void* const* d_in, const int* in_sizes, int n_in,
                              void* d_out, int out_size) {
    const float* sup   = (const float*)d_in[0];
    const float* qry   = (const float*)d_in[1];
    const int*   lab   = (const int*)d_in[2];
    const float* wk    = (const float*)d_in[3];
    const float* bk    = (const float*)d_in[4];
    const float* wv    = (const float*)d_in[5];
    const float* bv    = (const float*)d_in[6];
    const float* gamma = (const float*)d_in[7];
    const float* beta  = (const float*)d_in[8];
    float* out = (float*)d_out;

    cudaFuncSetAttribute(proj_kernel,  cudaFuncAttributeMaxDynamicSharedMemorySize, SMEM_BYTES);
    cudaFuncSetAttribute(score_kernel, cudaFuncAttributeMaxDynamicSharedMemorySize, SC_SMEM);
    cudaFuncSetAttribute(dist_kernel,  cudaFuncAttributeMaxDynamicSharedMemorySize, DS_SMEM);

    build_x_kernel<<<NROWS, 256>>>(sup, qry, out);
    proj_kernel<<<(NCOL + 31) / 32, 192, SMEM_BYTES>>>(wk, wv);
    assemble_kernel<<<dim3(NT, NSEQ), 256>>>(bk, bv, gamma, beta);
    score_kernel<<<dim3(5, 5, NSUP), 512, SC_SMEM>>>(lab);
    softmax_kernel<<<(NSUP * NT + 7) / 8, 256>>>();
    dist_kernel<<<dim3(5, 9, NSUP), 512, DS_SMEM>>>(lab, out);
}